// round 11
// baseline (speedup 1.0000x reference)
#include <cuda_runtime.h>

#define BATCH 8
typedef unsigned long long ull;

// Inter-kernel scratch (no allocations allowed). These symbols are ONLY
// referenced from device code — passing a __device__ symbol as a host-side
// kernel argument yields the host shadow address (the R5 bug).
__device__ float g_hidden[BATCH * 8192];            // [batch][8192]
__device__ float g_part[8 * BATCH * 8192];          // [split][batch][row]
__device__ int   g_ctr1[512];                        // k1 per-row-tile arrival counters
__device__ int   g_ctr2[128];                        // k2 per-row-tile arrival counters

__device__ __forceinline__ void fma2(ull &acc, ull a, ull b) {
    // packed fp32x2 FMA (Blackwell): acc.lo += a.lo*b.lo; acc.hi += a.hi*b.hi
    asm volatile("fma.rn.f32x2 %0, %1, %2, %0;" : "+l"(acc) : "l"(a), "l"(b));
}

__device__ __forceinline__ unsigned smem_u32(const void* p) {
    return (unsigned)__cvta_generic_to_shared(p);
}

__device__ __forceinline__ void cp_async16(unsigned dst, const void* src) {
    asm volatile("cp.async.ca.shared.global [%0], [%1], 16;" :: "r"(dst), "l"(src) : "memory");
}

// Split-K GEMV with fused last-block epilogue:
//   partial[(y*BATCH+b)*ROWS + row] = sum_{k in split y's KC chunk} W[row,k]*in[b,k]
//   last arriving split block for a row tile sums partials (fixed order: deterministic),
//   adds bias, optional tanh, writes dst[b*ROWS + row].
// in = concat(inA [BATCH, splitK], inB [BATCH, KFULL-splitK]); inA==nullptr -> g_hidden.
// Grid: x = row tiles (ROWS/(RPW*WARPS)), y = split index SPLITS = KFULL/KC.
template<int KFULL, int KC, int RPW, int WARPS, int CHUNK, int ROWS, bool TANH>
__global__ void __launch_bounds__(WARPS * 32, 3) gemv_fused_kernel(
    const float* __restrict__ W,
    const float* __restrict__ inA,
    const float* __restrict__ inB,
    int splitK,
    const float* __restrict__ bias,
    float* __restrict__ outArg)
{
    constexpr int NCH    = KC / CHUNK;
    constexpr int RPB    = RPW * WARPS;
    constexpr int SPLITS = KFULL / KC;
    static_assert(RPW * BATCH == 32, "one lane per (row,batch) output");
    static_assert(RPB * BATCH == WARPS * 32, "one thread per (row,batch) in epilogue");

    __shared__ float s_in[2][BATCH][CHUNK];
    __shared__ int s_last;

    const int tid  = threadIdx.x;
    const int lane = tid & 31;
    const int warp = tid >> 5;
    const int row0 = blockIdx.x * RPB + warp * RPW;
    const int koff = blockIdx.y * KC;

    const float* srcA = inA ? inA : (const float*)g_hidden;

    auto prefetch = [&](int buf, int c) {
        const int k0 = koff + c * CHUNK;
        constexpr int NV = BATCH * CHUNK / 4;   // float4 transfers
        #pragma unroll
        for (int i = tid; i < NV; i += WARPS * 32) {
            int b  = i / (CHUNK / 4);
            int kk = (i % (CHUNK / 4)) * 4;
            int kg = k0 + kk;
            const float* src = (kg < splitK)
                ? (srcA + (size_t)b * splitK + kg)
                : (inB  + (size_t)b * (KFULL - splitK) + (kg - splitK));
            cp_async16(smem_u32(&s_in[buf][b][kk]), src);
        }
        asm volatile("cp.async.commit_group;" ::: "memory");
    };

    ull acc[RPW][BATCH];
    #pragma unroll
    for (int r = 0; r < RPW; r++)
        #pragma unroll
        for (int b = 0; b < BATCH; b++)
            acc[r][b] = 0ull;

    prefetch(0, 0);
    if (NCH > 1) prefetch(1, 1);

    for (int c = 0; c < NCH; c++) {
        if (c + 1 < NCH) asm volatile("cp.async.wait_group 1;" ::: "memory");
        else             asm volatile("cp.async.wait_group 0;" ::: "memory");
        __syncthreads();

        const float* wbase = W + (size_t)row0 * KFULL + koff + c * CHUNK;
        const float* sbase = &s_in[c & 1][0][0];

        // Step covers 256 k per warp: lane owns 8 consecutive k.
        // 8 front-batched LDG.128 -> 4 KB/warp in flight; 12 warps/SM -> 48 KB,
        // far above the ~18 KB BW-latency product needed to saturate HBM.
        #pragma unroll
        for (int s = 0; s < CHUNK / 256; s++) {
            const int kk = s * 256 + lane * 8;
            ulonglong2 w0[RPW], w1[RPW];
            #pragma unroll
            for (int r = 0; r < RPW; r++) {
                const ulonglong2* p = (const ulonglong2*)(wbase + (size_t)r * KFULL + kk);
                w0[r] = __ldcs(p);
                w1[r] = __ldcs(p + 1);
            }
            #pragma unroll
            for (int b = 0; b < BATCH; b++) {
                ulonglong2 i0 = *(const ulonglong2*)(sbase + b * CHUNK + kk);
                ulonglong2 i1 = *(const ulonglong2*)(sbase + b * CHUNK + kk + 4);
                #pragma unroll
                for (int r = 0; r < RPW; r++) {
                    fma2(acc[r][b], w0[r].x, i0.x);
                    fma2(acc[r][b], w0[r].y, i0.y);
                    fma2(acc[r][b], w1[r].x, i1.x);
                    fma2(acc[r][b], w1[r].y, i1.y);
                }
            }
        }
        __syncthreads();
        if (c + 2 < NCH) prefetch(c & 1, c + 2);
    }

    // Cross-lane reduce: lane (r*8+b) ends owning partial (row0+r, batch b).
    float myval = 0.f;
    #pragma unroll
    for (int r = 0; r < RPW; r++) {
        #pragma unroll
        for (int b = 0; b < BATCH; b++) {
            float v = __uint_as_float((unsigned)(acc[r][b] & 0xffffffffu))
                    + __uint_as_float((unsigned)(acc[r][b] >> 32));
            #pragma unroll
            for (int off = 16; off; off >>= 1)
                v += __shfl_xor_sync(0xffffffffu, v, off);
            if (lane == r * BATCH + b) myval = v;
        }
    }
    {
        const int r   = lane / BATCH;
        const int b   = lane % BATCH;
        const int row = row0 + r;
        g_part[((size_t)blockIdx.y * BATCH + b) * ROWS + row] = myval;
    }

    // ---- Fused epilogue: last split block for this row tile finishes the sum ----
    __threadfence();          // make this block's partial writes globally visible
    __syncthreads();          // all 128 partials written before the count
    int* ctr = TANH ? g_ctr1 : g_ctr2;
    if (tid == 0) {
        int old = atomicAdd(&ctr[blockIdx.x], 1);
        s_last = (old == SPLITS - 1);
    }
    __syncthreads();
    if (s_last) {
        // thread tid -> (row = base + tid/8, batch = tid%8); 128 threads = 16x8 outputs
        const int r   = tid >> 3;
        const int b   = tid & 7;
        const int row = blockIdx.x * RPB + r;
        float v = bias[row];
        #pragma unroll
        for (int s = 0; s < SPLITS; s++)              // fixed order -> deterministic
            v += g_part[((size_t)s * BATCH + b) * ROWS + row];
        if (TANH) v = tanhf(v);
        float* dst = TANH ? (float*)g_hidden : outArg;
        dst[(size_t)b * ROWS + row] = v;
        if (tid == 0) ctr[blockIdx.x] = 0;            // reset for next graph replay
    }
}

extern "C" void kernel_launch(void* const* d_in, const int* in_sizes, int n_in,
                              void* d_out, int out_size) {
    const float* x     = (const float*)d_in[0];   // [8, 8192]
    const float* h0    = (const float*)d_in[1];   // [8, 8192]
    const float* w_i2h = (const float*)d_in[2];   // [8192, 16384]
    const float* b_i2h = (const float*)d_in[3];   // [8192]
    const float* w_h2o = (const float*)d_in[4];   // [2048, 8192]
    const float* b_h2o = (const float*)d_in[5];   // [2048]
    float* out = (float*)d_out;                   // [8, 2048]

    // Kernel 1: g_hidden = tanh(x@Wx^T + h0@Wh^T + b).
    // KFULL=16384, 4 splits of 4096; grid (512 row tiles, 4 splits).
    gemv_fused_kernel<16384, 4096, 4, 4, 512, 8192, true><<<dim3(512, 4), 128>>>(
        w_i2h, x, h0, 8192, b_i2h, nullptr);

    // Kernel 2: out = g_hidden@Wo^T + b.
    // KFULL=8192, 8 splits of 1024; grid (128 row tiles, 8 splits) = 1024 blocks
    // (short kernel: more blocks flatten the wave ramp).
    gemv_fused_kernel<8192, 1024, 4, 4, 512, 2048, false><<<dim3(128, 8), 128>>>(
        w_h2o, nullptr, x /*unused: splitK==KFULL*/, 8192, b_h2o, out);

    (void)in_sizes; (void)n_in; (void)out_size;
}

// round 12
// speedup vs baseline: 1.0795x; 1.0795x over previous
#include <cuda_runtime.h>

#define BATCH 8
typedef unsigned long long ull;

// Inter-kernel scratch (no allocations allowed). These symbols are ONLY
// referenced from device code — passing a __device__ symbol as a host-side
// kernel argument yields the host shadow address (the R5 bug).
__device__ float g_hidden[BATCH * 8192];            // [batch][8192]
__device__ float g_part[8 * BATCH * 8192];          // [split][batch][row]
__device__ int   g_ctr1[512];                        // k1 per-row-tile arrival counters
__device__ int   g_ctr2[128];                        // k2 per-row-tile arrival counters

__device__ __forceinline__ void fma2(ull &acc, ull a, ull b) {
    // packed fp32x2 FMA (Blackwell): acc.lo += a.lo*b.lo; acc.hi += a.hi*b.hi
    asm volatile("fma.rn.f32x2 %0, %1, %2, %0;" : "+l"(acc) : "l"(a), "l"(b));
}

__device__ __forceinline__ unsigned smem_u32(const void* p) {
    return (unsigned)__cvta_generic_to_shared(p);
}

__device__ __forceinline__ void cp_async16(unsigned dst, const void* src) {
    asm volatile("cp.async.ca.shared.global [%0], [%1], 16;" :: "r"(dst), "l"(src) : "memory");
}

// Split-K GEMV with fused last-block epilogue.
//   partial[(y*BATCH+b)*ROWS + row] = sum_{k in split y's KC chunk} W[row,k]*in[b,k]
//   Last arriving split block for a row tile sums partials in fixed order
//   (deterministic), adds bias, optional tanh, writes dst[b*ROWS + row].
// in = concat(inA [BATCH, splitK], inB [BATCH, KFULL-splitK]); inA==nullptr -> g_hidden.
// Grid: x = row tiles (ROWS/(RPW*WARPS)), y = split index, SPLITS = KFULL/KC.
template<int KFULL, int KC, int RPW, int WARPS, int CHUNK, int ROWS, bool TANH>
__global__ void __launch_bounds__(WARPS * 32, 4) gemv_fused_kernel(
    const float* __restrict__ W,
    const float* __restrict__ inA,
    const float* __restrict__ inB,
    int splitK,
    const float* __restrict__ bias,
    float* __restrict__ outArg)
{
    constexpr int NCH    = KC / CHUNK;
    constexpr int RPB    = RPW * WARPS;
    constexpr int SPLITS = KFULL / KC;
    static_assert(RPW * BATCH == 32, "one lane per (row,batch) output");
    static_assert(RPB * BATCH == WARPS * 32, "one thread per (row,batch) in epilogue");

    __shared__ float s_in[2][BATCH][CHUNK];
    __shared__ int s_last;

    const int tid  = threadIdx.x;
    const int lane = tid & 31;
    const int warp = tid >> 5;
    const int row0 = blockIdx.x * RPB + warp * RPW;
    const int koff = blockIdx.y * KC;

    const float* srcA = inA ? inA : (const float*)g_hidden;

    auto prefetch = [&](int buf, int c) {
        const int k0 = koff + c * CHUNK;
        constexpr int NV = BATCH * CHUNK / 4;   // float4 transfers
        #pragma unroll
        for (int i = tid; i < NV; i += WARPS * 32) {
            int b  = i / (CHUNK / 4);
            int kk = (i % (CHUNK / 4)) * 4;
            int kg = k0 + kk;
            const float* src = (kg < splitK)
                ? (srcA + (size_t)b * splitK + kg)
                : (inB  + (size_t)b * (KFULL - splitK) + (kg - splitK));
            cp_async16(smem_u32(&s_in[buf][b][kk]), src);
        }
        asm volatile("cp.async.commit_group;" ::: "memory");
    };

    ull acc[RPW][BATCH];
    #pragma unroll
    for (int r = 0; r < RPW; r++)
        #pragma unroll
        for (int b = 0; b < BATCH; b++)
            acc[r][b] = 0ull;

    prefetch(0, 0);
    if (NCH > 1) prefetch(1, 1);

    for (int c = 0; c < NCH; c++) {
        if (c + 1 < NCH) asm volatile("cp.async.wait_group 1;" ::: "memory");
        else             asm volatile("cp.async.wait_group 0;" ::: "memory");
        __syncthreads();

        const float* wbase = W + (size_t)row0 * KFULL + koff + c * CHUNK;
        const float* sbase = &s_in[c & 1][0][0];

        // Step covers 128 k per warp: lane owns 4 CONSECUTIVE floats (16B).
        // -> one fully-coalesced LDG.128 per row (contiguous 512B/warp) and
        //    conflict-free LDS.128 for inputs (contiguous 16B/lane).
        // 4 front-batched LDG.128 = 2 KB/warp in flight; 16 warps/SM -> 32 KB,
        // above the ~18 KB BW-latency product needed to saturate HBM.
        #pragma unroll
        for (int s = 0; s < CHUNK / 128; s++) {
            const int kk = s * 128 + lane * 4;
            ulonglong2 w[RPW];
            #pragma unroll
            for (int r = 0; r < RPW; r++)
                w[r] = __ldcs((const ulonglong2*)(wbase + (size_t)r * KFULL + kk));
            #pragma unroll
            for (int b = 0; b < BATCH; b++) {
                ulonglong2 iv = *(const ulonglong2*)(sbase + b * CHUNK + kk);
                #pragma unroll
                for (int r = 0; r < RPW; r++) {
                    fma2(acc[r][b], w[r].x, iv.x);
                    fma2(acc[r][b], w[r].y, iv.y);
                }
            }
        }
        __syncthreads();
        if (c + 2 < NCH) prefetch(c & 1, c + 2);
    }

    // Cross-lane reduce: lane (r*8+b) ends owning partial (row0+r, batch b).
    float myval = 0.f;
    #pragma unroll
    for (int r = 0; r < RPW; r++) {
        #pragma unroll
        for (int b = 0; b < BATCH; b++) {
            float v = __uint_as_float((unsigned)(acc[r][b] & 0xffffffffu))
                    + __uint_as_float((unsigned)(acc[r][b] >> 32));
            #pragma unroll
            for (int off = 16; off; off >>= 1)
                v += __shfl_xor_sync(0xffffffffu, v, off);
            if (lane == r * BATCH + b) myval = v;
        }
    }
    {
        const int r   = lane / BATCH;
        const int b   = lane % BATCH;
        const int row = row0 + r;
        g_part[((size_t)blockIdx.y * BATCH + b) * ROWS + row] = myval;
    }

    // ---- Fused epilogue: last split block for this row tile finishes the sum ----
    __threadfence();          // release: make this block's partials visible
    __syncthreads();          // all 128 partials written before the count
    int* ctr = TANH ? g_ctr1 : g_ctr2;
    if (tid == 0) {
        int old = atomicAdd(&ctr[blockIdx.x], 1);
        s_last = (old == SPLITS - 1);
    }
    __syncthreads();
    if (s_last) {
        __threadfence();      // acquire: see all other splits' partials
        // thread tid -> (row = base + tid/8, batch = tid%8); 128 threads = 16x8 outputs
        const int r   = tid >> 3;
        const int b   = tid & 7;
        const int row = blockIdx.x * RPB + r;
        float v = bias[row];
        #pragma unroll
        for (int s = 0; s < SPLITS; s++)              // fixed order -> deterministic
            v += g_part[((size_t)s * BATCH + b) * ROWS + row];
        if (TANH) v = tanhf(v);
        float* dst = TANH ? (float*)g_hidden : outArg;
        dst[(size_t)b * ROWS + row] = v;
        if (tid == 0) ctr[blockIdx.x] = 0;            // reset for next graph replay
    }
}

extern "C" void kernel_launch(void* const* d_in, const int* in_sizes, int n_in,
                              void* d_out, int out_size) {
    const float* x     = (const float*)d_in[0];   // [8, 8192]
    const float* h0    = (const float*)d_in[1];   // [8, 8192]
    const float* w_i2h = (const float*)d_in[2];   // [8192, 16384]
    const float* b_i2h = (const float*)d_in[3];   // [8192]
    const float* w_h2o = (const float*)d_in[4];   // [2048, 8192]
    const float* b_h2o = (const float*)d_in[5];   // [2048]
    float* out = (float*)d_out;                   // [8, 2048]

    // Kernel 1: g_hidden = tanh(x@Wx^T + h0@Wh^T + b).
    // KFULL=16384, 8 splits of 2048; grid (512 row tiles, 8 splits) = 4096 blocks
    // (short blocks shrink the ragged-tail cost at occ 4).
    gemv_fused_kernel<16384, 2048, 4, 4, 512, 8192, true><<<dim3(512, 8), 128>>>(
        w_i2h, x, h0, 8192, b_i2h, nullptr);

    // Kernel 2: out = g_hidden@Wo^T + b.
    // KFULL=8192, 4 splits of 2048; grid (128 row tiles, 4 splits) = 512 blocks
    // (~one wave at occ 4; fewer fence+atomic epilogues than 8-way).
    gemv_fused_kernel<8192, 2048, 4, 4, 512, 2048, false><<<dim3(128, 4), 128>>>(
        w_h2o, nullptr, x /*unused: splitK==KFULL*/, 8192, b_h2o, out);

    (void)in_sizes; (void)n_in; (void)out_size;
}

// round 13
// speedup vs baseline: 1.1451x; 1.0607x over previous
#include <cuda_runtime.h>

#define BATCH 8
typedef unsigned long long ull;

// Inter-kernel scratch (no allocations allowed). These symbols are ONLY
// referenced from device code — passing a __device__ symbol as a host-side
// kernel argument yields the host shadow address (the R5 bug).
__device__ float g_hidden[BATCH * 8192];             // [batch][8192]
__device__ float g_part[16 * BATCH * 8192];          // [split][batch][row], 4 MB
__device__ int   g_ctr1[256];                         // k1 per-row-tile arrival counters
__device__ int   g_ctr2[64];                          // k2 per-row-tile arrival counters

__device__ __forceinline__ void fma2(ull &acc, ull a, ull b) {
    // packed fp32x2 FMA (Blackwell): acc.lo += a.lo*b.lo; acc.hi += a.hi*b.hi
    asm volatile("fma.rn.f32x2 %0, %1, %2, %0;" : "+l"(acc) : "l"(a), "l"(b));
}

__device__ __forceinline__ unsigned smem_u32(const void* p) {
    return (unsigned)__cvta_generic_to_shared(p);
}

__device__ __forceinline__ void cp_async16(unsigned dst, const void* src) {
    asm volatile("cp.async.ca.shared.global [%0], [%1], 16;" :: "r"(dst), "l"(src) : "memory");
}

// Split-K GEMV, barrier-free mainloop + fused last-block epilogue.
//   Inputs for the block's whole KC range are staged to smem ONCE (32 KB),
//   then the mainloop runs with zero block-wide barriers: warps desynchronize
//   and keep LDGs continuously in flight (explicit double-buffered weights).
//   partial[(y*BATCH+b)*ROWS + row] = sum_{k in split y} W[row,k]*in[b,k]
//   Last arriving split block per row tile sums partials in fixed order
//   (deterministic), adds bias, optional tanh, writes dst[b*ROWS + row].
// in = concat(inA [BATCH, splitK], inB [BATCH, KFULL-splitK]); inA==nullptr -> g_hidden.
// Grid: x = row tiles (ROWS/(RPW*WARPS)), y = split, SPLITS = KFULL/KC.
template<int KFULL, int KC, int RPW, int WARPS, int ROWS, bool TANH>
__global__ void __launch_bounds__(WARPS * 32, 2) gemv_fused_kernel(
    const float* __restrict__ W,
    const float* __restrict__ inA,
    const float* __restrict__ inB,
    int splitK,
    const float* __restrict__ bias,
    float* __restrict__ outArg)
{
    constexpr int RPB    = RPW * WARPS;            // rows per block
    constexpr int SPLITS = KFULL / KC;
    constexpr int STEPS  = KC / 128;               // 128 k per warp per step
    static_assert(RPW * BATCH == 32, "one lane per (row,batch) output");
    static_assert(RPB * BATCH == WARPS * 32, "one thread per (row,batch) in epilogue");

    __shared__ float s_in[BATCH][KC];              // 32 KB for KC=1024
    __shared__ int s_last;

    const int tid  = threadIdx.x;
    const int lane = tid & 31;
    const int warp = tid >> 5;
    const int row0 = blockIdx.x * RPB + warp * RPW;
    const int koff = blockIdx.y * KC;

    const float* srcA = inA ? inA : (const float*)g_hidden;

    // ---- One-time input staging (only block-wide sync in the kernel) ----
    {
        constexpr int NV = BATCH * KC / 4;         // float4 transfers
        #pragma unroll
        for (int i = tid; i < NV; i += WARPS * 32) {
            int b  = i / (KC / 4);
            int kk = (i % (KC / 4)) * 4;
            int kg = koff + kk;
            const float* src = (kg < splitK)
                ? (srcA + (size_t)b * splitK + kg)
                : (inB  + (size_t)b * (KFULL - splitK) + (kg - splitK));
            cp_async16(smem_u32(&s_in[b][kk]), src);
        }
        asm volatile("cp.async.commit_group;" ::: "memory");
        asm volatile("cp.async.wait_group 0;" ::: "memory");
        __syncthreads();
    }

    // ---- Barrier-free mainloop: double-buffered weight LDG.128s ----
    ull acc[RPW][BATCH];
    #pragma unroll
    for (int r = 0; r < RPW; r++)
        #pragma unroll
        for (int b = 0; b < BATCH; b++)
            acc[r][b] = 0ull;

    // lane owns 4 CONSECUTIVE floats: coalesced LDG.128 (contiguous 512B/warp),
    // conflict-free LDS.128 (contiguous 16B/lane).
    const float* wbase = W + (size_t)row0 * KFULL + koff + lane * 4;

    ulonglong2 wc[RPW], wn[RPW];
    #pragma unroll
    for (int r = 0; r < RPW; r++)
        wc[r] = __ldcs((const ulonglong2*)(wbase + (size_t)r * KFULL));

    #pragma unroll
    for (int s = 0; s < STEPS; s++) {
        if (s + 1 < STEPS) {                       // prefetch next step's weights
            #pragma unroll
            for (int r = 0; r < RPW; r++)
                wn[r] = __ldcs((const ulonglong2*)(wbase + (size_t)r * KFULL + (s + 1) * 128));
        }
        const int kk = s * 128 + lane * 4;
        #pragma unroll
        for (int b = 0; b < BATCH; b++) {
            ulonglong2 iv = *(const ulonglong2*)(&s_in[b][kk]);
            #pragma unroll
            for (int r = 0; r < RPW; r++) {
                fma2(acc[r][b], wc[r].x, iv.x);
                fma2(acc[r][b], wc[r].y, iv.y);
            }
        }
        #pragma unroll
        for (int r = 0; r < RPW; r++)
            wc[r] = wn[r];
    }

    // Cross-lane reduce: lane (r*8+b) ends owning partial (row0+r, batch b).
    float myval = 0.f;
    #pragma unroll
    for (int r = 0; r < RPW; r++) {
        #pragma unroll
        for (int b = 0; b < BATCH; b++) {
            float v = __uint_as_float((unsigned)(acc[r][b] & 0xffffffffu))
                    + __uint_as_float((unsigned)(acc[r][b] >> 32));
            #pragma unroll
            for (int off = 16; off; off >>= 1)
                v += __shfl_xor_sync(0xffffffffu, v, off);
            if (lane == r * BATCH + b) myval = v;
        }
    }
    {
        const int r   = lane / BATCH;
        const int b   = lane % BATCH;
        const int row = row0 + r;
        g_part[((size_t)blockIdx.y * BATCH + b) * ROWS + row] = myval;
    }

    // ---- Fused epilogue: last split block for this row tile finishes the sum ----
    __threadfence();          // release: make this block's partials visible
    __syncthreads();          // all partials of this block written before the count
    int* ctr = TANH ? g_ctr1 : g_ctr2;
    if (tid == 0) {
        int old = atomicAdd(&ctr[blockIdx.x], 1);
        s_last = (old == SPLITS - 1);
    }
    __syncthreads();
    if (s_last) {
        __threadfence();      // acquire: see all other splits' partials
        // thread tid -> (row = base + tid/8, batch = tid%8)
        const int r   = tid >> 3;
        const int b   = tid & 7;
        const int row = blockIdx.x * RPB + r;
        float v = bias[row];
        #pragma unroll
        for (int s = 0; s < SPLITS; s++)              // fixed order -> deterministic
            v += g_part[((size_t)s * BATCH + b) * ROWS + row];
        if (TANH) v = tanhf(v);
        float* dst = TANH ? (float*)g_hidden : outArg;
        dst[(size_t)b * ROWS + row] = v;
        if (tid == 0) ctr[blockIdx.x] = 0;            // reset for next graph replay
    }
}

extern "C" void kernel_launch(void* const* d_in, const int* in_sizes, int n_in,
                              void* d_out, int out_size) {
    const float* x     = (const float*)d_in[0];   // [8, 8192]
    const float* h0    = (const float*)d_in[1];   // [8, 8192]
    const float* w_i2h = (const float*)d_in[2];   // [8192, 16384]
    const float* b_i2h = (const float*)d_in[3];   // [8192]
    const float* w_h2o = (const float*)d_in[4];   // [2048, 8192]
    const float* b_h2o = (const float*)d_in[5];   // [2048]
    float* out = (float*)d_out;                   // [8, 2048]

    // Kernel 1: g_hidden = tanh(x@Wx^T + h0@Wh^T + b).
    // KFULL=16384, KC=1024 (16 splits); 256 row tiles of 32 rows -> grid (256,16)=4096.
    gemv_fused_kernel<16384, 1024, 4, 8, 8192, true><<<dim3(256, 16), 256>>>(
        w_i2h, x, h0, 8192, b_i2h, nullptr);

    // Kernel 2: out = g_hidden@Wo^T + b.
    // KFULL=8192, KC=1024 (8 splits); 64 row tiles of 32 rows -> grid (64,8)=512.
    gemv_fused_kernel<8192, 1024, 4, 8, 2048, false><<<dim3(64, 8), 256>>>(
        w_h2o, nullptr, x /*unused: splitK==KFULL*/, 8192, b_h2o, out);

    (void)in_sizes; (void)n_in; (void)out_size;
}

// round 14
// speedup vs baseline: 1.1641x; 1.0166x over previous
#include <cuda_runtime.h>

#define BATCH 8
typedef unsigned long long ull;

// Inter-kernel scratch (no allocations allowed). These symbols are ONLY
// referenced from device code — passing a __device__ symbol as a host-side
// kernel argument yields the host shadow address (the R5 bug).
__device__ float g_hidden[BATCH * 8192];             // [batch][8192]
__device__ float g_part[16 * BATCH * 8192];          // [split][batch][row], 4 MB
__device__ int   g_ctr1[256];                         // k1 per-row-tile arrival counters
__device__ int   g_ctr2[64];                          // k2 per-row-tile arrival counters

__device__ __forceinline__ void fma2(ull &acc, ull a, ull b) {
    // packed fp32x2 FMA (Blackwell): acc.lo += a.lo*b.lo; acc.hi += a.hi*b.hi
    asm volatile("fma.rn.f32x2 %0, %1, %2, %0;" : "+l"(acc) : "l"(a), "l"(b));
}

// duplicate one fp32 into both halves of an f32x2 register pair
__device__ __forceinline__ ull dupf(unsigned w) {
    ull d;
    asm("mov.b64 %0, {%1, %1};" : "=l"(d) : "r"(w));
    return d;
}

// 1-bit XOR swizzle: makes the mainloop's 32B-strided LDS.128 pattern
// conflict-free (each 8-lane phase covers all 32 banks). 16B-granular.
__device__ __forceinline__ int swz(int off) {
    return off ^ ((off >> 3) & 0x10);
}

// Split-K GEMV, barrier-free mainloop, depth-2 weight prefetch, batch-paired
// accumulators, fused last-block epilogue.
//   Inputs for the block's whole KC range are staged ONCE into smem in
//   batch-PAIR-interleaved layout s_in[pair][k][2] (32 KB), then the mainloop
//   has zero block-wide barriers. Weights stream via 3 register stages of
//   4x LDG.128 (depth 2 => 4 KB/warp continuously in flight).
//   acc[r][p] = f32x2 accumulator for (row r, batches 2p / 2p+1).
//   partial[(y*BATCH+b)*ROWS + row] = sum_{k in split y} W[row,k]*in[b,k]
//   Last arriving split block per row tile sums partials in fixed order
//   (deterministic), adds bias, optional tanh, writes dst[b*ROWS + row].
// in = concat(inA [BATCH, splitK], inB [BATCH, KFULL-splitK]); inA==nullptr -> g_hidden.
// Grid: x = row tiles (ROWS/(RPW*WARPS)), y = split, SPLITS = KFULL/KC.
template<int KFULL, int KC, int RPW, int WARPS, int ROWS, bool TANH>
__global__ void __launch_bounds__(WARPS * 32, 2) gemv_fused_kernel(
    const float* __restrict__ W,
    const float* __restrict__ inA,
    const float* __restrict__ inB,
    int splitK,
    const float* __restrict__ bias,
    float* __restrict__ outArg)
{
    constexpr int RPB    = RPW * WARPS;            // rows per block
    constexpr int SPLITS = KFULL / KC;
    constexpr int STEPS  = KC / 128;               // 128 k per warp per step
    constexpr int NPAIR  = BATCH / 2;              // 4 batch pairs
    static_assert(RPW * BATCH == 32, "one lane per (row,batch) output");
    static_assert(RPB * BATCH == WARPS * 32, "one thread per (row,batch) in epilogue");

    // Pair-interleaved inputs: s_in[p][k][0]=in[2p][k], [1]=in[2p+1][k]. 32 KB.
    __shared__ float s_in[NPAIR][KC][2];
    __shared__ int s_last;

    const int tid  = threadIdx.x;
    const int lane = tid & 31;
    const int warp = tid >> 5;
    const int row0 = blockIdx.x * RPB + warp * RPW;
    const int koff = blockIdx.y * KC;

    const float* srcA = inA ? inA : (const float*)g_hidden;

    // ---- One-time input staging: LDG two batch rows, STS interleaved ----
    {
        constexpr int NU = NPAIR * (KC / 4);       // units of (pair, 4 k)
        char* sbytes = (char*)&s_in[0][0][0];
        #pragma unroll
        for (int u = tid; u < NU; u += WARPS * 32) {
            int p  = u / (KC / 4);
            int kl = (u % (KC / 4)) * 4;           // local k, 4-aligned
            int kg = koff + kl;
            const float* s0;
            const float* s1;
            if (kg < splitK) {
                s0 = srcA + (size_t)(2 * p)     * splitK + kg;
                s1 = srcA + (size_t)(2 * p + 1) * splitK + kg;
            } else {
                s0 = inB + (size_t)(2 * p)     * (KFULL - splitK) + (kg - splitK);
                s1 = inB + (size_t)(2 * p + 1) * (KFULL - splitK) + (kg - splitK);
            }
            float4 a = *(const float4*)s0;
            float4 b = *(const float4*)s1;
            char* base = sbytes + (size_t)p * (KC * 8);
            *(float4*)(base + swz(kl * 8))      = make_float4(a.x, b.x, a.y, b.y);
            *(float4*)(base + swz(kl * 8 + 16)) = make_float4(a.z, b.z, a.w, b.w);
        }
        __syncthreads();
    }

    // ---- Barrier-free mainloop: 3-stage (depth-2) weight prefetch ----
    ull acc[RPW][NPAIR];
    #pragma unroll
    for (int r = 0; r < RPW; r++)
        #pragma unroll
        for (int p = 0; p < NPAIR; p++)
            acc[r][p] = 0ull;

    // lane owns 4 CONSECUTIVE k: coalesced LDG.128 (contiguous 512B/warp/row).
    const float* wbase = W + (size_t)row0 * KFULL + koff + lane * 4;
    const char*  sbytes = (const char*)&s_in[0][0][0];

    uint4 wbuf[3][RPW];
    #pragma unroll
    for (int r = 0; r < RPW; r++) {
        wbuf[0][r] = __ldcs((const uint4*)(wbase + (size_t)r * KFULL));
        if (STEPS > 1)
            wbuf[1][r] = __ldcs((const uint4*)(wbase + (size_t)r * KFULL + 128));
    }

    #pragma unroll
    for (int s = 0; s < STEPS; s++) {
        if (s + 2 < STEPS) {                       // keep 2 stages in flight
            #pragma unroll
            for (int r = 0; r < RPW; r++)
                wbuf[(s + 2) % 3][r] =
                    __ldcs((const uint4*)(wbase + (size_t)r * KFULL + (s + 2) * 128));
        }
        const int kk = s * 128 + lane * 4;         // element index of lane's k0
        ulonglong2 ivA[NPAIR], ivB[NPAIR];
        #pragma unroll
        for (int p = 0; p < NPAIR; p++) {
            const char* base = sbytes + (size_t)p * (KC * 8);
            ivA[p] = *(const ulonglong2*)(base + swz(kk * 8));        // pairs k0,k1
            ivB[p] = *(const ulonglong2*)(base + swz(kk * 8 + 16));   // pairs k2,k3
        }
        #pragma unroll
        for (int r = 0; r < RPW; r++) {
            uint4 w = wbuf[s % 3][r];
            ull d0 = dupf(w.x), d1 = dupf(w.y), d2 = dupf(w.z), d3 = dupf(w.w);
            #pragma unroll
            for (int p = 0; p < NPAIR; p++) {
                fma2(acc[r][p], d0, ivA[p].x);
                fma2(acc[r][p], d1, ivA[p].y);
                fma2(acc[r][p], d2, ivB[p].x);
                fma2(acc[r][p], d3, ivB[p].y);
            }
        }
    }

    // Cross-lane reduce: lane (r*8+b) ends owning partial (row0+r, batch b).
    float myval = 0.f;
    #pragma unroll
    for (int r = 0; r < RPW; r++) {
        #pragma unroll
        for (int b = 0; b < BATCH; b++) {
            ull a = acc[r][b >> 1];
            float v = (b & 1) ? __uint_as_float((unsigned)(a >> 32))
                              : __uint_as_float((unsigned)(a & 0xffffffffu));
            #pragma unroll
            for (int off = 16; off; off >>= 1)
                v += __shfl_xor_sync(0xffffffffu, v, off);
            if (lane == r * BATCH + b) myval = v;
        }
    }
    {
        const int r   = lane / BATCH;
        const int b   = lane % BATCH;
        const int row = row0 + r;
        g_part[((size_t)blockIdx.y * BATCH + b) * ROWS + row] = myval;
    }

    // ---- Fused epilogue: last split block for this row tile finishes the sum ----
    __threadfence();          // release: make this block's partials visible
    __syncthreads();          // all partials of this block written before the count
    int* ctr = TANH ? g_ctr1 : g_ctr2;
    if (tid == 0) {
        int old = atomicAdd(&ctr[blockIdx.x], 1);
        s_last = (old == SPLITS - 1);
    }
    __syncthreads();
    if (s_last) {
        __threadfence();      // acquire: see all other splits' partials
        // thread tid -> (row = base + tid/8, batch = tid%8)
        const int r   = tid >> 3;
        const int b   = tid & 7;
        const int row = blockIdx.x * RPB + r;
        float v = bias[row];
        #pragma unroll
        for (int s = 0; s < SPLITS; s++)              // fixed order -> deterministic
            v += g_part[((size_t)s * BATCH + b) * ROWS + row];
        if (TANH) v = tanhf(v);
        float* dst = TANH ? (float*)g_hidden : outArg;
        dst[(size_t)b * ROWS + row] = v;
        if (tid == 0) ctr[blockIdx.x] = 0;            // reset for next graph replay
    }
}

extern "C" void kernel_launch(void* const* d_in, const int* in_sizes, int n_in,
                              void* d_out, int out_size) {
    const float* x     = (const float*)d_in[0];   // [8, 8192]
    const float* h0    = (const float*)d_in[1];   // [8, 8192]
    const float* w_i2h = (const float*)d_in[2];   // [8192, 16384]
    const float* b_i2h = (const float*)d_in[3];   // [8192]
    const float* w_h2o = (const float*)d_in[4];   // [2048, 8192]
    const float* b_h2o = (const float*)d_in[5];   // [2048]
    float* out = (float*)d_out;                   // [8, 2048]

    // Kernel 1: g_hidden = tanh(x@Wx^T + h0@Wh^T + b).
    // KFULL=16384, KC=1024 (16 splits); 256 row tiles of 32 rows -> grid (256,16).
    gemv_fused_kernel<16384, 1024, 4, 8, 8192, true><<<dim3(256, 16), 256>>>(
        w_i2h, x, h0, 8192, b_i2h, nullptr);

    // Kernel 2: out = g_hidden@Wo^T + b.
    // KFULL=8192, KC=1024 (8 splits); 64 row tiles of 32 rows -> grid (64,8).
    gemv_fused_kernel<8192, 1024, 4, 8, 2048, false><<<dim3(64, 8), 256>>>(
        w_h2o, nullptr, x /*unused: splitK==KFULL*/, 8192, b_h2o, out);

    (void)in_sizes; (void)n_in; (void)out_size;
}